// round 15
// baseline (speedup 1.0000x reference)
#include <cuda_runtime.h>
#include <cstdint>

// Problem constants
#define MAX_DIST 35.0f
#define BOX 71            // ceil(2*35/1 + 1)
#define FDIM 32
#define BATCH 8
#define NPTS 16384

#define NPOINTS (BATCH * NPTS)               // 131,072
#define NCELLS  (BOX * BOX * BOX)            // 357,911
#define NCELLS_PAD 357912                    // /4-aligned for int4 reset
#define SLICE0_F4 (NCELLS * (FDIM / 4))      // 2,863,288 float4 = slice 0
#define TOTAL_F4  (SLICE0_F4 * BATCH)        // 22,906,304

// Per-cell linked lists. Sentinel = 0; entries store pid+1.
__device__ int d_head[NCELLS_PAD];           // 1.4 MB
__device__ int d_next[NPOINTS];              // 0.5 MB

// Grid-barrier state for K01 (512 blocks, all co-resident).
// g_count self-resets within each call; g_gen is monotonic across replays.
__device__ unsigned g_count = 0;
__device__ unsigned g_gen = 0;

#define K01_BLOCKS (NPOINTS / 256)           // 512
#define K01_THREADS (K01_BLOCKS * 256)       // 131,072

// ---------------------------------------------------------------------------
// K01 (merged init + build): 512 blocks x 256 threads.
//   Phase A: zero d_head (int4 stripes, ~0.3us; also warms it into L2),
//   grid barrier (all 512 blocks trivially co-resident on 148 SMs),
//   Phase B: per-point cell = round-half-to-even(c+35) (faithful to
//     jnp.round); out-of-box points excluded (they add exactly +0.0 in the
//     reference). ALL B*N points map into batch slice 0 (reference's
//     tf.zeros batch column). atomicExch stores pid+1 (0 = end of list).
// ---------------------------------------------------------------------------
__global__ void __launch_bounds__(256)
init_build_kernel(const float* __restrict__ coords) {
    const int i = blockIdx.x * blockDim.x + threadIdx.x;  // 0 .. NPOINTS-1

    // Issue coord loads up front; latency hides under phase A + barrier.
    float c0 = __ldg(&coords[i * 3 + 0]);
    float c1 = __ldg(&coords[i * 3 + 1]);
    float c2 = __ldg(&coords[i * 3 + 2]);

    // ---- Phase A: zero head array (int4) ----
    int4* h4 = (int4*)d_head;
    const int n4 = NCELLS_PAD / 4;           // 89,478
    for (int j = i; j < n4; j += K01_THREADS) {
        h4[j] = make_int4(0, 0, 0, 0);
    }

    // ---- Grid barrier ----
    __threadfence();
    __syncthreads();
    if (threadIdx.x == 0) {
        unsigned my_gen = *(volatile unsigned*)&g_gen;
        if (atomicAdd(&g_count, 1) == K01_BLOCKS - 1) {
            g_count = 0;
            __threadfence();
            atomicAdd(&g_gen, 1);
        } else {
            while (*(volatile unsigned*)&g_gen == my_gen)
                __nanosleep(32);
        }
    }
    __syncthreads();

    // ---- Phase B: list build ----
    int g0 = __float2int_rn(c0 + MAX_DIST);
    int g1 = __float2int_rn(c1 + MAX_DIST);
    int g2 = __float2int_rn(c2 + MAX_DIST);
    if ((unsigned)g0 < BOX && (unsigned)g1 < BOX && (unsigned)g2 < BOX) {
        int cell = (g0 * BOX + g1) * BOX + g2;
        d_next[i] = atomicExch(&d_head[cell], i + 1);
    }
}

// ---------------------------------------------------------------------------
// K2 (PDL over K01): gather + zero. One thread per (cell, quad).
//   1. 6 zero batches into slices 1..6 (pre-sync; overlaps K01),
//   2. PDL sync, ISSUE the head load immediately,
//   3. 1 zero batch into slice 7 (hides head-load latency),
//   4. walk the cell's list accumulating feats[pid*8+q] (8 quad-threads of
//      a cell share one warp -> 128B-coalesced feature reads; head/next
//      L2-resident),
//   5. stream the accumulated float4 as the slice-0 value.
// Every output byte written exactly once; no atomics on the output.
// ---------------------------------------------------------------------------
__global__ void __launch_bounds__(256)
gather_zero_kernel(const float4* __restrict__ feats,
                   float* __restrict__ out) {
    const int tid = blockIdx.x * blockDim.x + threadIdx.x;
    if (tid >= SLICE0_F4) return;                  // 72 pad threads

    float4* out4 = (float4*)out;
    const float4 z = make_float4(0.f, 0.f, 0.f, 0.f);

    // Pre-sync zeros: slices 1..6 (274 MB grid-wide, covers K01 runtime).
    #pragma unroll
    for (int k = 1; k <= 6; k++) {
        __stcs(&out4[(long long)k * SLICE0_F4 + tid], z);
    }

    cudaGridDependencySynchronize();               // wait for K01's lists

    const int cell = tid >> 3;
    const int q = tid & 7;

    int e = d_head[cell];                          // issue load NOW (L2 hit)

    // One post-sync batch hides the head-load latency.
    __stcs(&out4[(long long)7 * SLICE0_F4 + tid], z);

    float4 acc = z;
    while (e != 0) {
        int pid = e - 1;
        float4 v = __ldg(&feats[(long long)pid * 8 + q]);
        acc.x += v.x; acc.y += v.y; acc.z += v.z; acc.w += v.w;
        e = d_next[pid];
    }
    __stcs(&out4[tid], acc);                       // slice 0, written once
}

extern "C" void kernel_launch(void* const* d_in, const int* in_sizes, int n_in,
                              void* d_out, int out_size) {
    const float* coords = (const float*)d_in[0];     // [8,16384,3] f32
    const float4* feats = (const float4*)d_in[1];    // [8,16384,32] f32 as float4
    float* out = (float*)d_out;                      // [8,71,71,71,32] f32

    // K01: merged head-reset + list-build (internal grid barrier).
    init_build_kernel<<<K01_BLOCKS, 256>>>(coords);

    // K2: gather + zero — PDL early launch over K01.
    cudaLaunchConfig_t cfg = {};
    cfg.gridDim = dim3((SLICE0_F4 + 255) / 256, 1, 1);  // 11185 blocks
    cfg.blockDim = dim3(256, 1, 1);
    cudaLaunchAttribute pdl[1];
    pdl[0].id = cudaLaunchAttributeProgrammaticStreamSerialization;
    pdl[0].val.programmaticStreamSerializationAllowed = 1;
    cfg.attrs = pdl; cfg.numAttrs = 1;
    cudaLaunchKernelEx(&cfg, gather_zero_kernel, feats, out);
}

// round 16
// speedup vs baseline: 1.0011x; 1.0011x over previous
#include <cuda_runtime.h>
#include <cstdint>

// Problem constants
#define MAX_DIST 35.0f
#define BOX 71            // ceil(2*35/1 + 1)
#define FDIM 32
#define BATCH 8
#define NPTS 16384

#define NPOINTS (BATCH * NPTS)               // 131,072
#define NCELLS  (BOX * BOX * BOX)            // 357,911
#define SLICE0_F4 (NCELLS * (FDIM / 4))      // 2,863,288 float4 = slice 0
#define TOTAL_F4  (SLICE0_F4 * BATCH)        // 22,906,304

#define HEAD_BYTES (NCELLS * 4)              // 1,431,644
#define HEAD_LINES ((HEAD_BYTES + 127) / 128)// 11,185 cache lines

// Per-cell linked lists. Sentinel = 0; entries store pid+1.
// INVARIANT: d_head is all-zero at entry of every kernel_launch call —
// zero-initialized on first use (CUDA zeroes __device__ globals), restored
// by K2's q==0 reset store on every call. Deterministic, replay-safe.
__device__ int d_head[NCELLS];               // 1.4 MB
__device__ int d_next[NPOINTS];              // 0.5 MB

// ---------------------------------------------------------------------------
// K1 (FIRST launch — no init kernel): build per-cell lists.
//   - first HEAD_LINES threads prefetch the head array into L2 so K2's
//     head reads are L2 hits (R12 showed cold DRAM head reads cost ~0.5us),
//   - cell = round-half-to-even(c+35) per axis (faithful to jnp.round),
//   - out-of-box points excluded (they add exactly +0.0 in the reference),
//   - ALL B*N points map into batch slice 0 (reference's tf.zeros batch
//     column),
//   - atomicExch stores pid+1 (0 = end of list).
// ---------------------------------------------------------------------------
__global__ void __launch_bounds__(256)
build_lists_kernel(const float* __restrict__ coords) {
    const int i = blockIdx.x * blockDim.x + threadIdx.x;  // 0 .. NPOINTS-1

    // Warm the head array into L2 (also helps our own atomicExch).
    if (i < HEAD_LINES) {
        const char* addr = (const char*)d_head + (size_t)i * 128;
        asm volatile("prefetch.global.L2 [%0];" :: "l"(addr));
    }

    float c0 = __ldg(&coords[i * 3 + 0]);
    float c1 = __ldg(&coords[i * 3 + 1]);
    float c2 = __ldg(&coords[i * 3 + 2]);
    int g0 = __float2int_rn(c0 + MAX_DIST);
    int g1 = __float2int_rn(c1 + MAX_DIST);
    int g2 = __float2int_rn(c2 + MAX_DIST);

    if ((unsigned)g0 < BOX && (unsigned)g1 < BOX && (unsigned)g2 < BOX) {
        int cell = (g0 * BOX + g1) * BOX + g2;
        d_next[i] = atomicExch(&d_head[cell], i + 1);
    }
}

// ---------------------------------------------------------------------------
// K2 (PDL over K1): gather + zero. One thread per (cell, quad).
//   1. 6 zero batches into slices 1..6 (pre-sync; overlaps K1),
//   2. PDL sync, ISSUE the head load immediately (L2 hit via K1's prefetch),
//   3. 1 zero batch into slice 7 (hides head-load latency; the proven
//      6+1 split from R14),
//   4. q==0 thread restores the cell's head to 0 (maintains the all-zero
//      invariant for the next replay; 8 quad-threads share one warp, all
//      read e before the reset store),
//   5. walk the cell's list accumulating feats[pid*8+q] (128B-coalesced
//      feature reads across the 8 quads),
//   6. stream the accumulated float4 as the slice-0 value.
// Every output byte written exactly once; no atomics on the output.
// ---------------------------------------------------------------------------
__global__ void __launch_bounds__(256)
gather_zero_kernel(const float4* __restrict__ feats,
                   float* __restrict__ out) {
    const int tid = blockIdx.x * blockDim.x + threadIdx.x;
    if (tid >= SLICE0_F4) return;                  // 72 pad threads

    float4* out4 = (float4*)out;
    const float4 z = make_float4(0.f, 0.f, 0.f, 0.f);

    // Pre-sync zeros: slices 1..6 (274 MB grid-wide, covers K1 runtime).
    #pragma unroll
    for (int k = 1; k <= 6; k++) {
        __stcs(&out4[(long long)k * SLICE0_F4 + tid], z);
    }

    cudaGridDependencySynchronize();               // wait for K1's lists

    const int cell = tid >> 3;
    const int q = tid & 7;

    int e = d_head[cell];                          // issue load NOW (L2 hit)

    // One post-sync batch hides the head-load latency.
    __stcs(&out4[(long long)7 * SLICE0_F4 + tid], z);

    if (q == 0 && e != 0) d_head[cell] = 0;        // restore invariant

    float4 acc = z;
    while (e != 0) {
        int pid = e - 1;
        float4 v = __ldg(&feats[(long long)pid * 8 + q]);
        acc.x += v.x; acc.y += v.y; acc.z += v.z; acc.w += v.w;
        e = d_next[pid];
    }
    __stcs(&out4[tid], acc);                       // slice 0, written once
}

extern "C" void kernel_launch(void* const* d_in, const int* in_sizes, int n_in,
                              void* d_out, int out_size) {
    const float* coords = (const float*)d_in[0];     // [8,16384,3] f32
    const float4* feats = (const float4*)d_in[1];    // [8,16384,32] f32 as float4
    float* out = (float*)d_out;                      // [8,71,71,71,32] f32

    // K1: build lists (first and only prerequisite kernel).
    build_lists_kernel<<<NPOINTS / 256, 256>>>(coords);

    // K2: gather + zero — PDL early launch over K1.
    cudaLaunchConfig_t cfg = {};
    cfg.gridDim = dim3((SLICE0_F4 + 255) / 256, 1, 1);  // 11185 blocks
    cfg.blockDim = dim3(256, 1, 1);
    cudaLaunchAttribute pdl[1];
    pdl[0].id = cudaLaunchAttributeProgrammaticStreamSerialization;
    pdl[0].val.programmaticStreamSerializationAllowed = 1;
    cfg.attrs = pdl; cfg.numAttrs = 1;
    cudaLaunchKernelEx(&cfg, gather_zero_kernel, feats, out);
}